// round 11
// baseline (speedup 1.0000x reference)
#include <cuda_runtime.h>
#include <cuda_bf16.h>
#include <cstdint>

#define NN 100000
#define EE 1600000
#define DD 128
#define GRID 148
#define TPB 1024
#define NTHREADS (GRID * TPB)
#define NWARPS (GRID * 32)
#define CHN 676                  // ceil(NN / GRID), <= TPB
#define TILES 782                // ceil(NN / 128)

// smem layout (bf16, rows padded to SP=136 elems = 272B -> ldmatrix conflict-free)
#define SP 136
#define OFF_XHI 0
#define OFF_XLO 34816
#define OFF_BHI 69632
#define OFF_BLO 104448
#define DSM_BYTES 139264

// ---------------- scratch (device globals; no allocations allowed) ----------
__device__ float g_y[(size_t)NN * DD];
__device__ float g_agg[(size_t)NN * DD];
__device__ int   g_degout[NN];
__device__ int   g_degin[NN];
__device__ int   g_rowstart[NN + 1];
__device__ int   g_fillc[NN];
__device__ int   g_csr[EE];
__device__ int   g_srcv[EE];
__device__ int   g_dstv[EE];
__device__ int   g_bsum[GRID];
__device__ int   g_boff[GRID];
__device__ int   g_is32;
__device__ int   g_count;
__device__ volatile int g_sense;

// ---------------- helpers -----------------------------------------------------
__device__ __forceinline__ uint32_t smem_u32(const void* p) {
    uint32_t a;
    asm("{ .reg .u64 t; cvta.to.shared.u64 t, %1; cvt.u32.u64 %0, t; }" : "=r"(a) : "l"(p));
    return a;
}
__device__ __forceinline__ uint32_t pk2(float a, float b) {   // low half = a
    __nv_bfloat162 t = __floats2bfloat162_rn(a, b);
    return *reinterpret_cast<uint32_t*>(&t);
}
__device__ __forceinline__ void ldsm_x4(uint32_t* r, uint32_t addr) {
    asm volatile("ldmatrix.sync.aligned.m8n8.x4.shared.b16 {%0,%1,%2,%3}, [%4];"
                 : "=r"(r[0]), "=r"(r[1]), "=r"(r[2]), "=r"(r[3]) : "r"(addr));
}
__device__ __forceinline__ void ldsm_x2(uint32_t* r, uint32_t addr) {
    asm volatile("ldmatrix.sync.aligned.m8n8.x2.shared.b16 {%0,%1}, [%2];"
                 : "=r"(r[0]), "=r"(r[1]) : "r"(addr));
}
__device__ __forceinline__ void mma16816(float* d, const uint32_t* a, const uint32_t* b) {
    asm volatile("mma.sync.aligned.m16n8k16.row.col.f32.bf16.bf16.f32 "
                 "{%0,%1,%2,%3}, {%4,%5,%6,%7}, {%8,%9}, {%0,%1,%2,%3};"
                 : "+f"(d[0]), "+f"(d[1]), "+f"(d[2]), "+f"(d[3])
                 : "r"(a[0]), "r"(a[1]), "r"(a[2]), "r"(a[3]), "r"(b[0]), "r"(b[1]));
}

// ---------------- software grid barrier --------------------------------------
__device__ __forceinline__ void grid_barrier(int& parity) {
    int next = parity ^ 1;
    __threadfence();
    __syncthreads();
    if (threadIdx.x == 0) {
        if (atomicAdd(&g_count, 1) == GRID - 1) {
            atomicExch(&g_count, 0);
            __threadfence();
            g_sense = next;
        } else {
            while (g_sense != next) __nanosleep(64);
        }
    }
    __syncthreads();
    __threadfence();
    parity = next;
}

// ---------------- tensor-core GEMM phase (mma.sync bf16x3, 32 warps) ----------
// Y[i,:] = (X[i,:] @ W) * rsqrt(max(degout[i],1))
// Warp tile 16 rows x 32 cols: wr = wid>>2 (0..7), wc = wid&3.
__device__ void gemm_tc(const float* __restrict__ X, const float* __restrict__ W,
                        float* __restrict__ Y, char* dsm)
{
    const uint32_t sbase = smem_u32(dsm);
    const int tid  = threadIdx.x;
    const int lane = tid & 31;
    const int wid  = tid >> 5;

    // ---- build B hi/lo once per phase: Bs[n][k] = W[k][n] ----
    for (int idx = tid; idx < DD * DD; idx += TPB) {
        int k = idx >> 7, n = idx & 127;         // idx = k*128 + n, coalesced over n
        float w = W[idx];
        float hf = __bfloat162float(__float2bfloat16(w));
        uint32_t o = (uint32_t)(n * SP + k) * 2u;
        *(__nv_bfloat16*)(dsm + OFF_BHI + o) = __float2bfloat16(hf);
        *(__nv_bfloat16*)(dsm + OFF_BLO + o) = __float2bfloat16(w - hf);
    }
    __syncthreads();

    const int wr = wid >> 2, wc = wid & 3;
    const uint32_t aRow = (uint32_t)(wr * 16 + (lane & 15));
    const uint32_t aK8  = (uint32_t)((lane >> 4) * 8);
    const uint32_t bN   = (uint32_t)(wc * 32 + (lane & 7));
    const uint32_t bK8  = (uint32_t)((lane & 8) ? 8 : 0);

    for (int tile = blockIdx.x; tile < TILES; tile += GRID) {
        const int i0 = tile * 128;

        // ---- X tile -> Xhi/Xlo smem: warp w owns rows 4w..4w+3 ----
        {
            char* ph = dsm + OFF_XHI + (size_t)lane * 8;
            char* pl = dsm + OFF_XLO + (size_t)lane * 8;
            #pragma unroll
            for (int r = 0; r < 4; r++) {
                int row = i0 + wid * 4 + r;
                bool ok = row < NN;
                float4 v = ok ? *(const float4*)(X + (size_t)row * DD + lane * 4)
                              : make_float4(0.f, 0.f, 0.f, 0.f);
                float hx = __bfloat162float(__float2bfloat16(v.x));
                float hy = __bfloat162float(__float2bfloat16(v.y));
                float hz = __bfloat162float(__float2bfloat16(v.z));
                float hw = __bfloat162float(__float2bfloat16(v.w));
                size_t ro = (size_t)(wid * 4 + r) * SP * 2;
                *(uint2*)(ph + ro) = make_uint2(pk2(hx, hy), pk2(hz, hw));
                *(uint2*)(pl + ro) = make_uint2(pk2(v.x - hx, v.y - hy),
                                                pk2(v.z - hz, v.w - hw));
            }
        }
        __syncthreads();

        // ---- 3-pass MMA: Ahi*Bhi + Ahi*Blo + Alo*Bhi ----
        float d[4][4];
        #pragma unroll
        for (int nt = 0; nt < 4; nt++)
            #pragma unroll
            for (int q = 0; q < 4; q++) d[nt][q] = 0.f;

        #pragma unroll
        for (int pass = 0; pass < 3; pass++) {
            const uint32_t xs = sbase + ((pass == 2) ? OFF_XLO : OFF_XHI);
            const uint32_t bs = sbase + ((pass == 1) ? OFF_BLO : OFF_BHI);
            #pragma unroll
            for (int kt = 0; kt < 8; kt++) {
                uint32_t a0[4];
                ldsm_x4(a0, xs + (aRow * SP + kt * 16 + aK8) * 2);
                #pragma unroll
                for (int nt = 0; nt < 4; nt++) {
                    uint32_t b[2];
                    ldsm_x2(b, bs + ((bN + nt * 8) * SP + kt * 16 + bK8) * 2);
                    mma16816(d[nt], a0, b);
                }
            }
        }

        // ---- epilogue: scale by rsqrt(degout) and store ----
        {
            const int gr = lane >> 2, qc = (lane & 3) * 2;
            #pragma unroll
            for (int half = 0; half < 2; half++) {
                int row = i0 + wr * 16 + gr + half * 8;
                if (row < NN) {
                    float po = rsqrtf(fmaxf((float)g_degout[row], 1.f));
                    float* yr = Y + (size_t)row * DD + wc * 32 + qc;
                    #pragma unroll
                    for (int nt = 0; nt < 4; nt++) {
                        float2 o;
                        o.x = d[nt][half * 2 + 0] * po;
                        o.y = d[nt][half * 2 + 1] * po;
                        *(float2*)(yr + nt * 8) = o;
                    }
                }
            }
        }
        __syncthreads();      // protect X smem before next tile overwrites
    }
}

// ---------------- aggregation phase (MLP-8 gather pipeline) -------------------
__device__ void aggregate_phase(const float* __restrict__ Yin, float* __restrict__ Out,
                                const float* __restrict__ bias) {
    const int lane = threadIdx.x & 31;
    const int gw   = blockIdx.x * (TPB / 32) + (threadIdx.x >> 5);
    float4 bb = *(const float4*)(bias + lane * 4);

    for (int node = gw; node < NN; node += NWARPS) {
        const int s0 = g_rowstart[node];
        const int s1 = g_rowstart[node + 1];
        float4 acc = make_float4(0.f, 0.f, 0.f, 0.f);
        for (int base = s0; base < s1; base += 32) {
            int rem = s1 - base;
            int idx = 0;
            if (lane < rem) idx = g_csr[base + lane];
            int cnt = rem < 32 ? rem : 32;
            int j = 0;
            for (; j + 8 <= cnt; j += 8) {                // 8 outstanding LDG.128
                float4 v[8];
                #pragma unroll
                for (int u = 0; u < 8; u++) {
                    int a = __shfl_sync(0xffffffffu, idx, j + u);
                    v[u] = *(const float4*)(Yin + (size_t)a * DD + lane * 4);
                }
                #pragma unroll
                for (int u = 0; u < 8; u++) {
                    acc.x += v[u].x; acc.y += v[u].y;
                    acc.z += v[u].z; acc.w += v[u].w;
                }
            }
            for (; j + 4 <= cnt; j += 4) {
                float4 v[4];
                #pragma unroll
                for (int u = 0; u < 4; u++) {
                    int a = __shfl_sync(0xffffffffu, idx, j + u);
                    v[u] = *(const float4*)(Yin + (size_t)a * DD + lane * 4);
                }
                #pragma unroll
                for (int u = 0; u < 4; u++) {
                    acc.x += v[u].x; acc.y += v[u].y;
                    acc.z += v[u].z; acc.w += v[u].w;
                }
            }
            for (; j < cnt; j++) {
                int a = __shfl_sync(0xffffffffu, idx, j);
                float4 v = *(const float4*)(Yin + (size_t)a * DD + lane * 4);
                acc.x += v.x; acc.y += v.y; acc.z += v.z; acc.w += v.w;
            }
        }
        float dn = rsqrtf(fmaxf((float)g_degin[node], 1.f));
        float4 o;
        o.x = fmaf(acc.x, dn, bb.x);
        o.y = fmaf(acc.y, dn, bb.y);
        o.z = fmaf(acc.z, dn, bb.z);
        o.w = fmaf(acc.w, dn, bb.w);
        *(float4*)(Out + (size_t)node * DD + lane * 4) = o;
    }
}

// ---------------- the single persistent kernel --------------------------------
__global__ __launch_bounds__(TPB) void gcn_mega(
    const float* __restrict__ in_feat, const void* __restrict__ ei,
    const float* __restrict__ W1, const float* __restrict__ b1,
    const float* __restrict__ W2, const float* __restrict__ b2,
    float* __restrict__ out)
{
    extern __shared__ char dsm[];
    __shared__ int si[TPB];
    const int tid  = threadIdx.x;
    const int gtid = blockIdx.x * TPB + tid;
    int parity = 0;

    // ---- P1: zero counters + dtype detect (block 0) ----
    for (int i = gtid; i < NN; i += NTHREADS) {
        g_degout[i] = 0; g_degin[i] = 0; g_fillc[i] = 0;
    }
    if (blockIdx.x == 0) {
        int bad = 0;
        const long long* p = (const long long*)ei;
        for (int j = tid; j < 2048; j += TPB) {
            long long v = p[j];
            if (v < 0 || v >= NN) bad = 1;
        }
        bad = __syncthreads_or(bad);
        if (tid == 0) g_is32 = bad;
    }
    grid_barrier(parity);                                          // B1

    // ---- P2: decode edges + degree histogram ----
    {
        const int is32 = g_is32;
        for (int e = gtid; e < EE; e += NTHREADS) {
            int s, d;
            if (is32) {
                const int* p = (const int*)ei;
                s = p[e]; d = p[EE + e];
            } else {
                const long long* p = (const long long*)ei;
                s = (int)p[e]; d = (int)p[EE + e];
            }
            g_srcv[e] = s; g_dstv[e] = d;
            atomicAdd(&g_degout[s], 1);
            atomicAdd(&g_degin[d], 1);
        }
    }
    grid_barrier(parity);                                          // B2

    // ---- P3: per-block in-degree sums ----
    {
        const int nb = blockIdx.x * CHN;
        const int ne = min(nb + CHN, NN);
        int s = 0;
        for (int i = nb + tid; i < ne; i += TPB) s += g_degin[i];
        si[tid] = s;
        __syncthreads();
        for (int off = TPB / 2; off > 0; off >>= 1) {
            if (tid < off) si[tid] += si[tid + off];
            __syncthreads();
        }
        if (tid == 0) g_bsum[blockIdx.x] = si[0];
    }
    grid_barrier(parity);                                          // B3

    // ---- P4: exclusive scan of block sums ----
    if (blockIdx.x == 0 && tid == 0) {
        int acc = 0;
        for (int b = 0; b < GRID; b++) { g_boff[b] = acc; acc += g_bsum[b]; }
    }
    grid_barrier(parity);                                          // B4

    // ---- P5: per-block exclusive scan -> g_rowstart (1 node/thread) ----
    {
        const int nb = blockIdx.x * CHN;
        const int ne = min(nb + CHN, NN);
        const int node = nb + tid;
        int v0 = (node < ne) ? g_degin[node] : 0;
        si[tid] = v0;
        __syncthreads();
        for (int off = 1; off < TPB; off <<= 1) {
            int x = (tid >= off) ? si[tid - off] : 0;
            __syncthreads();
            si[tid] += x;
            __syncthreads();
        }
        if (node < ne)
            g_rowstart[node] = ((tid > 0) ? si[tid - 1] : 0) + g_boff[blockIdx.x];
        if (blockIdx.x == 0 && tid == 0) g_rowstart[NN] = EE;
    }
    grid_barrier(parity);                                          // B5

    // ---- P6: CSR fill ----
    for (int e = gtid; e < EE; e += NTHREADS) {
        int d = g_dstv[e];
        int pos = atomicAdd(&g_fillc[d], 1);
        g_csr[g_rowstart[d] + pos] = g_srcv[e];
    }
    grid_barrier(parity);                                          // B6

    // ---- P7..P10: two GCN layers ----
    gemm_tc(in_feat, W1, g_y, dsm);
    grid_barrier(parity);                                          // B7
    aggregate_phase(g_y, g_agg, b1);
    grid_barrier(parity);                                          // B8
    gemm_tc(g_agg, W2, g_y, dsm);
    grid_barrier(parity);                                          // B9
    aggregate_phase(g_y, out, b2);
    grid_barrier(parity);                                          // B10 (parity restore)
}

// ---------------- launch: ONE graph node --------------------------------------
extern "C" void kernel_launch(void* const* d_in, const int* in_sizes, int n_in,
                              void* d_out, int out_size) {
    const float* in_feat = (const float*)d_in[0];
    const void*  ei      = d_in[1];
    const float* W1      = (const float*)d_in[2];
    const float* b1      = (const float*)d_in[3];
    const float* W2      = (const float*)d_in[4];
    const float* b2      = (const float*)d_in[5];
    float*       out     = (float*)d_out;

    cudaFuncSetAttribute(gcn_mega, cudaFuncAttributeMaxDynamicSharedMemorySize, DSM_BYTES);
    gcn_mega<<<GRID, TPB, DSM_BYTES>>>(in_feat, ei, W1, b1, W2, b2, out);
}

// round 12
// speedup vs baseline: 1.2655x; 1.2655x over previous
#include <cuda_runtime.h>
#include <cuda_bf16.h>
#include <cstdint>

#define NN 100000
#define EE 1600000
#define DD 128
#define GRID 148
#define TPB 512
#define NWARPS (GRID * 16)
#define CHN 676                  // ceil(NN / GRID)
#define TILES 782                // ceil(NN / 128)

// smem layout (bf16, rows padded to SP=136 elems = 272B -> ldmatrix conflict-free)
#define SP 136
#define OFF_XHI 0
#define OFF_XLO 34816
#define OFF_BHI 69632
#define OFF_BLO 104448
#define DSM_BYTES 139264

// ---------------- scratch (device globals; no allocations allowed) ----------
__device__ float g_y[(size_t)NN * DD];
__device__ float g_agg[(size_t)NN * DD];
__device__ int   g_degout[NN];
__device__ int   g_degin[NN];
__device__ float g_dof[NN];               // rsqrt(max(degout,1)) precomputed
__device__ float g_dif[NN];               // rsqrt(max(degin,1))  precomputed
__device__ int   g_rowstart[NN + 1];
__device__ int   g_fillc[NN];
__device__ int   g_csr[EE];
__device__ int   g_srcv[EE];
__device__ int   g_dstv[EE];
__device__ int   g_bsum[GRID];
__device__ int   g_boff[GRID];
__device__ int   g_is32;
__device__ int   g_count;                 // full grid barrier
__device__ volatile int g_sense;
__device__ int   g_count2;                // half-grid barrier (prep half)
__device__ volatile int g_sense2;

// ---------------- helpers -----------------------------------------------------
__device__ __forceinline__ uint32_t smem_u32(const void* p) {
    uint32_t a;
    asm("{ .reg .u64 t; cvta.to.shared.u64 t, %1; cvt.u32.u64 %0, t; }" : "=r"(a) : "l"(p));
    return a;
}
__device__ __forceinline__ uint32_t pk2(float a, float b) {   // low half = a
    __nv_bfloat162 t = __floats2bfloat162_rn(a, b);
    return *reinterpret_cast<uint32_t*>(&t);
}
__device__ __forceinline__ void ldsm_x4(uint32_t* r, uint32_t addr) {
    asm volatile("ldmatrix.sync.aligned.m8n8.x4.shared.b16 {%0,%1,%2,%3}, [%4];"
                 : "=r"(r[0]), "=r"(r[1]), "=r"(r[2]), "=r"(r[3]) : "r"(addr));
}
__device__ __forceinline__ void ldsm_x2(uint32_t* r, uint32_t addr) {
    asm volatile("ldmatrix.sync.aligned.m8n8.x2.shared.b16 {%0,%1}, [%2];"
                 : "=r"(r[0]), "=r"(r[1]) : "r"(addr));
}
__device__ __forceinline__ void mma16816(float* d, const uint32_t* a, const uint32_t* b) {
    asm volatile("mma.sync.aligned.m16n8k16.row.col.f32.bf16.bf16.f32 "
                 "{%0,%1,%2,%3}, {%4,%5,%6,%7}, {%8,%9}, {%0,%1,%2,%3};"
                 : "+f"(d[0]), "+f"(d[1]), "+f"(d[2]), "+f"(d[3])
                 : "r"(a[0]), "r"(a[1]), "r"(a[2]), "r"(a[3]), "r"(b[0]), "r"(b[1]));
}

// ---------------- full-grid barrier (all 512 threads) -------------------------
__device__ __forceinline__ void grid_barrier(int& parity) {
    int next = parity ^ 1;
    __threadfence();
    __syncthreads();
    if (threadIdx.x == 0) {
        if (atomicAdd(&g_count, 1) == GRID - 1) {
            atomicExch(&g_count, 0);
            __threadfence();
            g_sense = next;
        } else {
            while (g_sense != next) __nanosleep(64);
        }
    }
    __syncthreads();
    __threadfence();
    parity = next;
}

// ---------------- half-grid barrier (threads 0..255 of every block) -----------
__device__ __forceinline__ void half_barrier(int& par2) {
    int next = par2 ^ 1;
    __threadfence();
    asm volatile("bar.sync 2, 256;" ::: "memory");
    if (threadIdx.x == 0) {
        if (atomicAdd(&g_count2, 1) == GRID - 1) {
            atomicExch(&g_count2, 0);
            __threadfence();
            g_sense2 = next;
        } else {
            while (g_sense2 != next) __nanosleep(64);
        }
    }
    asm volatile("bar.sync 2, 256;" ::: "memory");
    __threadfence();
    par2 = next;
}

// ---------------- tensor-core GEMM (mma.sync bf16x3, NW warps) ----------------
// Y[i,:] = (X[i,:] @ W) [* g_dof[i] if SCALE_OUT]
// Participating threads: tid in [wbase*32, wbase*32 + NW*32).
template<int NW, int BAR_ID, bool SCALE_OUT>
__device__ void gemm_tc(const float* __restrict__ X, const float* __restrict__ W,
                        float* __restrict__ Y, char* dsm, int wbase)
{
    constexpr int NTHR = NW * 32;
    constexpr int NCPW = 128 / (NW / 4);        // cols/warp: NW16->32, NW8->64
    constexpr int NTN  = NCPW / 8;              // 4 or 8
    constexpr int RPW  = 128 / NW;              // x-fill rows/warp: 8 or 16
    const uint32_t sbase = smem_u32(dsm);
    const int tid  = threadIdx.x;
    const int ltid = tid - wbase * 32;
    const int lane = tid & 31;
    const int lw   = ltid >> 5;

    // ---- build B hi/lo once per phase: Bs[n][k] = W[k][n] ----
    for (int idx = ltid; idx < DD * DD; idx += NTHR) {
        int k = idx >> 7, n = idx & 127;
        float w = W[idx];
        float hf = __bfloat162float(__float2bfloat16(w));
        uint32_t o = (uint32_t)(n * SP + k) * 2u;
        *(__nv_bfloat16*)(dsm + OFF_BHI + o) = __float2bfloat16(hf);
        *(__nv_bfloat16*)(dsm + OFF_BLO + o) = __float2bfloat16(w - hf);
    }
    asm volatile("bar.sync %0, %1;" :: "n"(BAR_ID), "n"(NTHR) : "memory");

    const int wr = lw / (NW / 4);               // 0..3 (row group of 32)
    const int wc = lw % (NW / 4);               // col group of NCPW
    const uint32_t aRow = (uint32_t)(wr * 32 + (lane & 15));
    const uint32_t aK8  = (uint32_t)((lane >> 4) * 8);
    const uint32_t bN   = (uint32_t)(wc * NCPW + (lane & 7));
    const uint32_t bK8  = (uint32_t)((lane & 8) ? 8 : 0);

    for (int tile = blockIdx.x; tile < TILES; tile += GRID) {
        const int i0 = tile * 128;

        // ---- X tile -> Xhi/Xlo smem: warp lw owns rows lw*RPW.. ----
        {
            char* ph = dsm + OFF_XHI + (size_t)lane * 8;
            char* pl = dsm + OFF_XLO + (size_t)lane * 8;
            #pragma unroll
            for (int r = 0; r < RPW; r++) {
                int row = i0 + lw * RPW + r;
                bool ok = row < NN;
                float4 v = ok ? *(const float4*)(X + (size_t)row * DD + lane * 4)
                              : make_float4(0.f, 0.f, 0.f, 0.f);
                float hx = __bfloat162float(__float2bfloat16(v.x));
                float hy = __bfloat162float(__float2bfloat16(v.y));
                float hz = __bfloat162float(__float2bfloat16(v.z));
                float hw = __bfloat162float(__float2bfloat16(v.w));
                size_t ro = (size_t)(lw * RPW + r) * SP * 2;
                *(uint2*)(ph + ro) = make_uint2(pk2(hx, hy), pk2(hz, hw));
                *(uint2*)(pl + ro) = make_uint2(pk2(v.x - hx, v.y - hy),
                                                pk2(v.z - hz, v.w - hw));
            }
        }
        asm volatile("bar.sync %0, %1;" :: "n"(BAR_ID), "n"(NTHR) : "memory");

        // ---- 3-pass MMA: Ahi*Bhi + Ahi*Blo + Alo*Bhi ----
        float d[2][NTN][4];
        #pragma unroll
        for (int mt = 0; mt < 2; mt++)
            #pragma unroll
            for (int nt = 0; nt < NTN; nt++)
                #pragma unroll
                for (int q = 0; q < 4; q++) d[mt][nt][q] = 0.f;

        #pragma unroll
        for (int pass = 0; pass < 3; pass++) {
            const uint32_t xs = sbase + ((pass == 2) ? OFF_XLO : OFF_XHI);
            const uint32_t bs = sbase + ((pass == 1) ? OFF_BLO : OFF_BHI);
            #pragma unroll
            for (int kt = 0; kt < 8; kt++) {
                uint32_t a0[4], a1[4];
                ldsm_x4(a0, xs + (aRow * SP + kt * 16 + aK8) * 2);
                ldsm_x4(a1, xs + ((aRow + 16) * SP + kt * 16 + aK8) * 2);
                #pragma unroll
                for (int nt = 0; nt < NTN; nt++) {
                    uint32_t b[2];
                    ldsm_x2(b, bs + ((bN + nt * 8) * SP + kt * 16 + bK8) * 2);
                    mma16816(d[0][nt], a0, b);
                    mma16816(d[1][nt], a1, b);
                }
            }
        }

        // ---- epilogue ----
        {
            const int gr = lane >> 2, qc = (lane & 3) * 2;
            #pragma unroll
            for (int mt = 0; mt < 2; mt++) {
                #pragma unroll
                for (int half = 0; half < 2; half++) {
                    int row = i0 + wr * 32 + mt * 16 + gr + half * 8;
                    if (row < NN) {
                        float po = SCALE_OUT ? g_dof[row] : 1.f;
                        float* yr = Y + (size_t)row * DD + wc * NCPW + qc;
                        #pragma unroll
                        for (int nt = 0; nt < NTN; nt++) {
                            float2 o;
                            o.x = d[mt][nt][half * 2 + 0] * po;
                            o.y = d[mt][nt][half * 2 + 1] * po;
                            *(float2*)(yr + nt * 8) = o;
                        }
                    }
                }
            }
        }
        asm volatile("bar.sync %0, %1;" :: "n"(BAR_ID), "n"(NTHR) : "memory");
    }
}

// ---------------- aggregation (MLP-8; optional per-edge dout) -----------------
// Out[i,:] = g_dif[i] * sum_e (dout[src]?) * Y[csr[e],:] + bias
template<bool EDOUT>
__device__ void aggregate_phase(const float* __restrict__ Yin, float* __restrict__ Out,
                                const float* __restrict__ bias) {
    const int lane = threadIdx.x & 31;
    const int gw   = blockIdx.x * (TPB / 32) + (threadIdx.x >> 5);
    float4 bb = *(const float4*)(bias + lane * 4);

    for (int node = gw; node < NN; node += NWARPS) {
        const int s0 = g_rowstart[node];
        const int s1 = g_rowstart[node + 1];
        float4 acc = make_float4(0.f, 0.f, 0.f, 0.f);
        for (int base = s0; base < s1; base += 32) {
            int rem = s1 - base;
            int idx = 0;
            float dv = 0.f;
            if (lane < rem) {
                idx = g_csr[base + lane];
                if (EDOUT) dv = g_dof[idx];
            }
            int cnt = rem < 32 ? rem : 32;
            int j = 0;
            for (; j + 8 <= cnt; j += 8) {
                float4 v[8]; float w[8];
                #pragma unroll
                for (int u = 0; u < 8; u++) {
                    int a = __shfl_sync(0xffffffffu, idx, j + u);
                    w[u] = EDOUT ? __shfl_sync(0xffffffffu, dv, j + u) : 1.f;
                    v[u] = *(const float4*)(Yin + (size_t)a * DD + lane * 4);
                }
                #pragma unroll
                for (int u = 0; u < 8; u++) {
                    acc.x = fmaf(v[u].x, w[u], acc.x);
                    acc.y = fmaf(v[u].y, w[u], acc.y);
                    acc.z = fmaf(v[u].z, w[u], acc.z);
                    acc.w = fmaf(v[u].w, w[u], acc.w);
                }
            }
            for (; j < cnt; j++) {
                int a = __shfl_sync(0xffffffffu, idx, j);
                float w = EDOUT ? __shfl_sync(0xffffffffu, dv, j) : 1.f;
                float4 v = *(const float4*)(Yin + (size_t)a * DD + lane * 4);
                acc.x = fmaf(v.x, w, acc.x);
                acc.y = fmaf(v.y, w, acc.y);
                acc.z = fmaf(v.z, w, acc.z);
                acc.w = fmaf(v.w, w, acc.w);
            }
        }
        float dn = g_dif[node];
        float4 o;
        o.x = fmaf(acc.x, dn, bb.x);
        o.y = fmaf(acc.y, dn, bb.y);
        o.z = fmaf(acc.z, dn, bb.z);
        o.w = fmaf(acc.w, dn, bb.w);
        *(float4*)(Out + (size_t)node * DD + lane * 4) = o;
    }
}

// ---------------- the single persistent kernel --------------------------------
__global__ __launch_bounds__(TPB) void gcn_mega(
    const float* __restrict__ in_feat, const void* __restrict__ ei,
    const float* __restrict__ W1, const float* __restrict__ b1,
    const float* __restrict__ W2, const float* __restrict__ b2,
    float* __restrict__ out)
{
    extern __shared__ char dsm[];
    __shared__ int si[256];
    const int tid  = threadIdx.x;
    const int gtid = blockIdx.x * TPB + tid;
    int parity = 0;
    int par2 = 0;

    // ---- P1: zero counters + dtype detect (block 0) ----
    for (int i = gtid; i < NN; i += GRID * TPB) {
        g_degout[i] = 0; g_degin[i] = 0; g_fillc[i] = 0;
    }
    if (blockIdx.x == 0) {
        int bad = 0;
        const long long* p = (const long long*)ei;
        for (int j = tid; j < 2048; j += TPB) {
            long long v = p[j];
            if (v < 0 || v >= NN) bad = 1;
        }
        bad = __syncthreads_or(bad);
        if (tid == 0) g_is32 = bad;
    }
    grid_barrier(parity);                                          // B1

    // ================= PHASE II: prep (tid<256) || gemm1 (tid>=256) ==========
    if (tid < 256) {
        // ---- decode edges + degree histogram (8 warps) ----
        {
            const int is32 = g_is32;
            for (int e = blockIdx.x * 256 + tid; e < EE; e += GRID * 256) {
                int s, d;
                if (is32) {
                    const int* p = (const int*)ei;
                    s = p[e]; d = p[EE + e];
                } else {
                    const long long* p = (const long long*)ei;
                    s = (int)p[e]; d = (int)p[EE + e];
                }
                g_srcv[e] = s; g_dstv[e] = d;
                atomicAdd(&g_degout[s], 1);
                atomicAdd(&g_degin[d], 1);
            }
        }
        half_barrier(par2);                                        // S1

        // ---- per-block in-degree sums ----
        {
            const int nb = blockIdx.x * CHN;
            const int ne = min(nb + CHN, NN);
            int s = 0;
            for (int i = nb + tid; i < ne; i += 256) s += g_degin[i];
            si[tid] = s;
            asm volatile("bar.sync 2, 256;" ::: "memory");
            for (int off = 128; off > 0; off >>= 1) {
                if (tid < off) si[tid] += si[tid + off];
                asm volatile("bar.sync 2, 256;" ::: "memory");
            }
            if (tid == 0) g_bsum[blockIdx.x] = si[0];
        }
        half_barrier(par2);                                        // S2

        // ---- exclusive scan of block sums ----
        if (blockIdx.x == 0 && tid == 0) {
            int acc = 0;
            for (int b = 0; b < GRID; b++) { g_boff[b] = acc; acc += g_bsum[b]; }
        }
        half_barrier(par2);                                        // S3

        // ---- per-block rowstart scan (3 nodes/thread) + norm precompute ----
        {
            const int nb = blockIdx.x * CHN;
            const int ne = min(nb + CHN, NN);
            const int tb = nb + tid * 3;
            int v0 = 0, v1 = 0, v2 = 0;
            if (tb + 0 < ne) v0 = g_degin[tb + 0];
            if (tb + 1 < ne) v1 = g_degin[tb + 1];
            if (tb + 2 < ne) v2 = g_degin[tb + 2];
            si[tid] = v0 + v1 + v2;
            asm volatile("bar.sync 2, 256;" ::: "memory");
            for (int off = 1; off < 256; off <<= 1) {
                int x = (tid >= off) ? si[tid - off] : 0;
                asm volatile("bar.sync 2, 256;" ::: "memory");
                si[tid] += x;
                asm volatile("bar.sync 2, 256;" ::: "memory");
            }
            int excl = ((tid > 0) ? si[tid - 1] : 0) + g_boff[blockIdx.x];
            if (tb + 0 < ne) { g_rowstart[tb + 0] = excl; excl += v0; }
            if (tb + 1 < ne) { g_rowstart[tb + 1] = excl; excl += v1; }
            if (tb + 2 < ne) { g_rowstart[tb + 2] = excl; }
            if (blockIdx.x == 0 && tid == 0) g_rowstart[NN] = EE;
            for (int i = nb + tid; i < ne; i += 256) {
                g_dof[i] = rsqrtf(fmaxf((float)g_degout[i], 1.f));
                g_dif[i] = rsqrtf(fmaxf((float)g_degin[i],  1.f));
            }
        }
        half_barrier(par2);                                        // S4

        // ---- CSR fill ----
        for (int e = blockIdx.x * 256 + tid; e < EE; e += GRID * 256) {
            int d = g_dstv[e];
            int pos = atomicAdd(&g_fillc[d], 1);
            g_csr[g_rowstart[d] + pos] = g_srcv[e];
        }
    } else {
        // ---- gemm1 (8 warps): y1 = in_feat @ W1 (unscaled) ----
        gemm_tc<8, 1, false>(in_feat, W1, g_y, dsm, 8);
    }
    grid_barrier(parity);                                          // B2

    // ---- aggregate 1: h1 = dif * S(dof[src]*y1) + b1 ----
    aggregate_phase<true>(g_y, g_agg, b1);
    grid_barrier(parity);                                          // B3

    // ---- gemm2 (16 warps): y2 = (h1 @ W2) * dof ----
    gemm_tc<16, 3, true>(g_agg, W2, g_y, dsm, 0);
    grid_barrier(parity);                                          // B4

    // ---- aggregate 2: out = dif * S(y2) + b2 ----
    aggregate_phase<false>(g_y, out, b2);
    grid_barrier(parity);                                          // B5
    grid_barrier(parity);                                          // B6 (even count -> sense restored)
}

// ---------------- launch: ONE graph node --------------------------------------
extern "C" void kernel_launch(void* const* d_in, const int* in_sizes, int n_in,
                              void* d_out, int out_size) {
    const float* in_feat = (const float*)d_in[0];
    const void*  ei      = d_in[1];
    const float* W1      = (const float*)d_in[2];
    const float* b1      = (const float*)d_in[3];
    const float* W2      = (const float*)d_in[4];
    const float* b2      = (const float*)d_in[5];
    float*       out     = (float*)d_out;

    cudaFuncSetAttribute(gcn_mega, cudaFuncAttributeMaxDynamicSharedMemorySize, DSM_BYTES);
    gcn_mega<<<GRID, TPB, DSM_BYTES>>>(in_feat, ei, W1, b1, W2, b2, out);
}